// round 13
// baseline (speedup 1.0000x reference)
#include <cuda_runtime.h>
#include <cuda_bf16.h>
#include <mma.h>
#include <math.h>
#include <stdint.h>

using namespace nvcuda;

// ---------------- problem constants ----------------
constexpr int NN  = 50000;
constexpr int EE  = 800000;
constexpr int HD  = 256;
constexpr int BB  = 256;
constexpr int ND  = 5000;
constexpr int KK  = 16;
constexpr int ER  = 20000;

// ---------------- device scratch (zero-init at load; tail_zero restores each replay) ----
__device__ __align__(16) float g_h[(size_t)NN * HD];
__device__ __align__(16) float g_emb[(size_t)NN * HD];
__device__ __align__(16) __nv_bfloat16 g_xhi[(size_t)NN * HD];
__device__ __align__(16) __nv_bfloat16 g_xlo[(size_t)NN * HD];
__device__ __align__(16) __nv_bfloat16 g_acthi[(size_t)NN * HD];
__device__ __align__(16) __nv_bfloat16 g_actlo[(size_t)NN * HD];
__device__ __align__(16) __nv_bfloat16 g_w1hi[256 * 256];
__device__ __align__(16) __nv_bfloat16 g_w1lo[256 * 256];
__device__ __align__(16) __nv_bfloat16 g_w2hi[256 * 256];
__device__ __align__(16) __nv_bfloat16 g_w2lo[256 * 256];
__device__ float g_ssrcA[NN];
__device__ float g_sdstA[NN];
__device__ float g_ssrcB[NN];
__device__ float g_sdstB[NN];
__device__ int   g_deg[NN];
__device__ int   g_cursor[NN];
__device__ int   g_rowptr[NN + 1];
__device__ int   g_csr_src[EE];
__device__ int   g_cnt[3 * ND];

constexpr int PB = 128;
constexpr int CHUNK = (NN + PB - 1) / PB;  // 391
__device__ int g_part[PB];

// chunking of the node dimension for agg1/gemm2 pipelining
constexpr int BM = 128, BN = 128, KC = 32;
constexpr int TILES_TOTAL = (NN + BM - 1) / BM;  // 391
constexpr int TILES_C0 = 196;
constexpr int TILES_C1 = TILES_TOTAL - TILES_C0; // 195
constexpr int ROWS_C0 = TILES_C0 * BM;           // 25088

// ---------------- helpers ----------------
__device__ __forceinline__ uint32_t smem_u32(const void* p) {
    uint32_t a;
    asm("{ .reg .u64 t; cvta.to.shared.u64 t, %1; cvt.u32.u64 %0, t; }" : "=r"(a) : "l"(p));
    return a;
}
__device__ __forceinline__ void cp16(uint32_t dst, const void* src) {
    asm volatile("cp.async.cg.shared.global [%0], [%1], 16;" :: "r"(dst), "l"(src));
}

// ---------------- prep: x split + W1/W2 splits ----------------
__global__ void prep_all_kernel(const float* __restrict__ x,
                                const float* __restrict__ W1,
                                const float* __restrict__ W2) {
    int i = blockIdx.x * blockDim.x + threadIdx.x;
    if (i < NN * HD) {
        float v = x[i];
        __nv_bfloat16 h = __float2bfloat16(v);
        g_xhi[i] = h;
        g_xlo[i] = __float2bfloat16(v - __bfloat162float(h));
    }
    if (i < 256 * 256) {
        float v1 = W1[i];
        __nv_bfloat16 h1 = __float2bfloat16(v1);
        g_w1hi[i] = h1;
        g_w1lo[i] = __float2bfloat16(v1 - __bfloat162float(h1));
        float v2 = W2[i];
        __nv_bfloat16 h2 = __float2bfloat16(v2);
        g_w2hi[i] = h2;
        g_w2lo[i] = __float2bfloat16(v2 - __bfloat162float(h2));
    }
    if (i == 0) g_rowptr[NN] = EE;
}

// ---------------- fused histograms (deg/cnt are zero on entry) ----------------
__global__ void hist_kernel(const int* __restrict__ dst, const int* __restrict__ res) {
    int e = blockIdx.x * blockDim.x + threadIdx.x;
    if (e < EE) atomicAdd(&g_deg[dst[e]], 1);
    if (e < 3 * ER) atomicAdd(&g_cnt[(e / ER) * ND + res[e]], 1);
}

__global__ void partial_kernel() {
    __shared__ int sh[256];
    int b = blockIdx.x, t = threadIdx.x;
    int base = b * CHUNK;
    int s = 0;
    for (int i = t; i < CHUNK; i += 256) {
        int idx = base + i;
        if (idx < NN) s += g_deg[idx];
    }
    sh[t] = s;
    __syncthreads();
    for (int off = 128; off; off >>= 1) {
        if (t < off) sh[t] += sh[t + off];
        __syncthreads();
    }
    if (t == 0) g_part[b] = sh[0];
}

__global__ void rowptr_kernel() {
    __shared__ int red[128];
    __shared__ int s[512];
    int b = blockIdx.x, t = threadIdx.x;
    if (t < 128) red[t] = (t < b) ? g_part[t] : 0;
    __syncthreads();
    for (int off = 64; off; off >>= 1) {
        if (t < off) red[t] += red[t + off];
        __syncthreads();
    }
    int base = red[0];
    int idx = b * CHUNK + t;
    int v = (t < CHUNK && idx < NN) ? g_deg[idx] : 0;
    s[t] = v;
    __syncthreads();
    for (int off = 1; off < 512; off <<= 1) {
        int u = (t >= off) ? s[t - off] : 0;
        __syncthreads();
        s[t] += u;
        __syncthreads();
    }
    if (t < CHUNK && idx < NN) g_rowptr[idx] = base + s[t] - v;
}

__global__ void scatter_kernel(const int* __restrict__ src, const int* __restrict__ dst) {
    int e = blockIdx.x * blockDim.x + threadIdx.x;
    if (e < EE) {
        int d = dst[e];
        int pos = atomicAdd(&g_cursor[d], 1);
        g_csr_src[g_rowptr[d] + pos] = src[e];
    }
}

// ---------------- tail state-restore (runs on s2, overlapped with decode) ----------
__global__ void tail_zero_kernel() {
    int i = blockIdx.x * blockDim.x + threadIdx.x;
    if (i < NN) {
        g_ssrcA[i] = 0.f; g_sdstA[i] = 0.f;
        g_ssrcB[i] = 0.f; g_sdstB[i] = 0.f;
        g_deg[i] = 0; g_cursor[i] = 0;
    }
    if (i < 3 * ND) g_cnt[i] = 0;
}

// ---------------- WMMA bf16 GEMM, 3xBF16, cp.async 2-buffer, fused attention dots ----
constexpr int LDA = KC + 8;
constexpr int LDB = BN + 8;
constexpr int SZ_A = BM * LDA * 2;
constexpr int SZ_B = KC * LDB * 2;
constexpr int OFF_AH = 0;
constexpr int OFF_AL = SZ_A;
constexpr int OFF_BH = 2 * SZ_A;
constexpr int OFF_BL = 2 * SZ_A + SZ_B;
constexpr int BUF = 2 * SZ_A + 2 * SZ_B;   // 37888
constexpr int SMEM_GEMM = 2 * BUF;         // 75776

template <int LAYER>
__global__ __launch_bounds__(256, 2) void gemm_tc(const float* __restrict__ asrc,
                                                  const float* __restrict__ adst,
                                                  int row_base, int M) {
    const __nv_bfloat16* __restrict__ Ahi = (LAYER == 1) ? g_xhi : g_acthi;
    const __nv_bfloat16* __restrict__ Alo = (LAYER == 1) ? g_xlo : g_actlo;
    const __nv_bfloat16* __restrict__ Whi = (LAYER == 1) ? g_w1hi : g_w2hi;
    const __nv_bfloat16* __restrict__ Wlo = (LAYER == 1) ? g_w1lo : g_w2lo;
    float* __restrict__ ssrc = (LAYER == 1) ? g_ssrcA : g_ssrcB;
    float* __restrict__ sdst = (LAYER == 1) ? g_sdstA : g_sdstB;

    extern __shared__ char smem[];
    uint32_t sb = smem_u32(smem);

    int tid = threadIdx.x;
    int wid = tid >> 5;
    int lane = tid & 31;
    int wm = wid & 3;
    int wn = wid >> 2;
    int row0 = row_base + blockIdx.x * BM;
    int col0 = blockIdx.y * BN;

    wmma::fragment<wmma::accumulator, 16, 16, 16, float> acc[2][4];
#pragma unroll
    for (int mt = 0; mt < 2; mt++)
#pragma unroll
        for (int nt = 0; nt < 4; nt++) wmma::fill_fragment(acc[mt][nt], 0.0f);

    auto load_chunk = [&](int c) {
        int kc = c * KC;
        uint32_t bb = sb + (c & 1) * BUF;
#pragma unroll
        for (int p = 0; p < 2; p++) {
            int t = p * 256 + tid;
            int r = t >> 2, seg = t & 3;
            int gr = row0 + r; if (gr >= M) gr = M - 1;
            size_t go = (size_t)gr * 256 + kc + seg * 8;
            uint32_t so = r * (LDA * 2) + seg * 16;
            cp16(bb + OFF_AH + so, Ahi + go);
            cp16(bb + OFF_AL + so, Alo + go);
        }
#pragma unroll
        for (int p = 0; p < 2; p++) {
            int t = p * 256 + tid;
            int k = t >> 4, seg = t & 15;
            size_t go = (size_t)(kc + k) * 256 + col0 + seg * 8;
            uint32_t so = k * (LDB * 2) + seg * 16;
            cp16(bb + OFF_BH + so, Whi + go);
            cp16(bb + OFF_BL + so, Wlo + go);
        }
        asm volatile("cp.async.commit_group;" ::: "memory");
    };

    load_chunk(0);

    for (int c = 0; c < 8; c++) {
        if (c < 7) {
            load_chunk(c + 1);
            asm volatile("cp.async.wait_group 1;" ::: "memory");
        } else {
            asm volatile("cp.async.wait_group 0;" ::: "memory");
        }
        __syncthreads();

        const char* buf = smem + (c & 1) * BUF;
        const __nv_bfloat16* bAh = (const __nv_bfloat16*)(buf + OFF_AH);
        const __nv_bfloat16* bAl = (const __nv_bfloat16*)(buf + OFF_AL);
        const __nv_bfloat16* bBh = (const __nv_bfloat16*)(buf + OFF_BH);
        const __nv_bfloat16* bBl = (const __nv_bfloat16*)(buf + OFF_BL);

#pragma unroll
        for (int s = 0; s < KC / 16; s++) {
            wmma::fragment<wmma::matrix_a, 16, 16, 16, __nv_bfloat16, wmma::row_major> ah[2], al[2];
#pragma unroll
            for (int mt = 0; mt < 2; mt++) {
                wmma::load_matrix_sync(ah[mt], bAh + (wm * 32 + mt * 16) * LDA + s * 16, LDA);
                wmma::load_matrix_sync(al[mt], bAl + (wm * 32 + mt * 16) * LDA + s * 16, LDA);
            }
#pragma unroll
            for (int nt = 0; nt < 4; nt++) {
                wmma::fragment<wmma::matrix_b, 16, 16, 16, __nv_bfloat16, wmma::row_major> bh, bl;
                wmma::load_matrix_sync(bh, bBh + (s * 16) * LDB + wn * 64 + nt * 16, LDB);
                wmma::load_matrix_sync(bl, bBl + (s * 16) * LDB + wn * 64 + nt * 16, LDB);
#pragma unroll
                for (int mt = 0; mt < 2; mt++) {
                    wmma::mma_sync(acc[mt][nt], ah[mt], bh, acc[mt][nt]);
                    wmma::mma_sync(acc[mt][nt], ah[mt], bl, acc[mt][nt]);
                    wmma::mma_sync(acc[mt][nt], al[mt], bh, acc[mt][nt]);
                }
            }
        }
        __syncthreads();
    }

    // ---- epilogue: stage C tile in smem, write g_h, fused partial dots ----
    float* smem_f = (float*)smem;  // 128 x 132 fp32 = 67584 B
#pragma unroll
    for (int mt = 0; mt < 2; mt++)
#pragma unroll
        for (int nt = 0; nt < 4; nt++)
            wmma::store_matrix_sync(smem_f + (wm * 32 + mt * 16) * 132 + wn * 64 + nt * 16,
                                    acc[mt][nt], 132, wmma::mem_row_major);
    __syncthreads();

    float4 af = *(const float4*)(asrc + col0 + lane * 4);
    float4 df = *(const float4*)(adst + col0 + lane * 4);
#pragma unroll 4
    for (int rr = 0; rr < 16; rr++) {
        int r = wid * 16 + rr;
        int grow = row0 + r;
        if (grow < M) {
            float4 v = *(float4*)(smem_f + r * 132 + lane * 4);
            *(float4*)(g_h + (size_t)grow * 256 + col0 + lane * 4) = v;
            float s1 = v.x * af.x + v.y * af.y + v.z * af.z + v.w * af.w;
            float s2 = v.x * df.x + v.y * df.y + v.z * df.z + v.w * df.w;
#pragma unroll
            for (int o = 16; o; o >>= 1) {
                s1 += __shfl_xor_sync(0xffffffffu, s1, o);
                s2 += __shfl_xor_sync(0xffffffffu, s2, o);
            }
            if (lane == 0) {
                atomicAdd(&ssrc[grow], s1);   // exactly 2 contributions -> deterministic
                atomicAdd(&sdst[grow], s2);
            }
        }
    }
}

// ---------------- fused GAT softmax + aggregation, warp per dst, node range ----------
__device__ __forceinline__ float leaky02(float s) { return s > 0.f ? s : 0.2f * s; }

template <int LAYER>
__global__ __launch_bounds__(256) void gat_aggregate_kernel(const float* __restrict__ bias,
                                                            int n0, int ncount) {
    const float* __restrict__ ssrc = (LAYER == 1) ? g_ssrcA : g_ssrcB;
    const float* __restrict__ sdst = (LAYER == 1) ? g_sdstA : g_sdstB;

    int gw = (blockIdx.x * blockDim.x + threadIdx.x) >> 5;
    int lane = threadIdx.x & 31;
    if (gw >= ncount) return;
    int w = n0 + gw;

    int base = g_rowptr[w];
    int d = g_rowptr[w + 1] - base;
    float4 acc0 = make_float4(0.f, 0.f, 0.f, 0.f);
    float4 acc1 = make_float4(0.f, 0.f, 0.f, 0.f);

    if (d > 0) {
        float sdv = sdst[w];
        int myidx = 0;
        float e = -1e30f;
        if (lane < d) {
            myidx = g_csr_src[base + lane];
            e = leaky02(ssrc[myidx] + sdv);
        }
        float mx = e;
        for (int i = 32 + lane; i < d; i += 32)
            mx = fmaxf(mx, leaky02(ssrc[g_csr_src[base + i]] + sdv));
#pragma unroll
        for (int o = 16; o; o >>= 1) mx = fmaxf(mx, __shfl_xor_sync(0xffffffffu, mx, o));
        float p = (lane < d) ? __expf(e - mx) : 0.f;
        float z = p;
        for (int i = 32 + lane; i < d; i += 32)
            z += __expf(leaky02(ssrc[g_csr_src[base + i]] + sdv) - mx);
#pragma unroll
        for (int o = 16; o; o >>= 1) z += __shfl_xor_sync(0xffffffffu, z, o);
        float invz = 1.f / (z + 1e-16f);
        float pn = p * invz;

        int dcap = d < 32 ? d : 32;
#pragma unroll 4
        for (int i = 0; i < dcap; i++) {
            float a = __shfl_sync(0xffffffffu, pn, i);
            int src = __shfl_sync(0xffffffffu, myidx, i);
            const float4* hp = (const float4*)(g_h + (size_t)src * 256);
            float4 v0 = hp[lane];
            float4 v1 = hp[32 + lane];
            acc0.x += a * v0.x; acc0.y += a * v0.y; acc0.z += a * v0.z; acc0.w += a * v0.w;
            acc1.x += a * v1.x; acc1.y += a * v1.y; acc1.z += a * v1.z; acc1.w += a * v1.w;
        }
        for (int i = 32; i < d; i++) {
            int src = g_csr_src[base + i];
            float a = __expf(leaky02(ssrc[src] + sdv) - mx) * invz;
            const float4* hp = (const float4*)(g_h + (size_t)src * 256);
            float4 v0 = hp[lane];
            float4 v1 = hp[32 + lane];
            acc0.x += a * v0.x; acc0.y += a * v0.y; acc0.z += a * v0.z; acc0.w += a * v0.w;
            acc1.x += a * v1.x; acc1.y += a * v1.y; acc1.z += a * v1.z; acc1.w += a * v1.w;
        }
    }

    const float4* b4 = (const float4*)bias;
    float4 bb0 = b4[lane], bb1 = b4[32 + lane];
    acc0.x += bb0.x; acc0.y += bb0.y; acc0.z += bb0.z; acc0.w += bb0.w;
    acc1.x += bb1.x; acc1.y += bb1.y; acc1.z += bb1.z; acc1.w += bb1.w;

    if (LAYER == 1) {
        float v[8] = {acc0.x, acc0.y, acc0.z, acc0.w, acc1.x, acc1.y, acc1.z, acc1.w};
#pragma unroll
        for (int j = 0; j < 8; j++) v[j] = v[j] / (1.f + __expf(-v[j]));
        size_t o0 = (size_t)w * 256 + lane * 4;
#pragma unroll
        for (int j = 0; j < 4; j++) {
            __nv_bfloat16 h = __float2bfloat16(v[j]);
            g_acthi[o0 + j] = h;
            g_actlo[o0 + j] = __float2bfloat16(v[j] - __bfloat162float(h));
        }
        size_t o1 = o0 + 128;
#pragma unroll
        for (int j = 0; j < 4; j++) {
            __nv_bfloat16 h = __float2bfloat16(v[4 + j]);
            g_acthi[o1 + j] = h;
            g_actlo[o1 + j] = __float2bfloat16(v[4 + j] - __bfloat162float(h));
        }
    } else {
        float4* o4 = (float4*)(g_emb + (size_t)w * 256);
        o4[lane] = acc0;
        o4[32 + lane] = acc1;
    }
}

// ---------------- sequential per-triplet scan, smem-prefetched indices ----------------
__global__ void scan_seq_kernel(const int* __restrict__ head, const int* __restrict__ rel,
                                const int* __restrict__ g2l, const int* __restrict__ nb,
                                const float* __restrict__ wts) {
    __shared__ int   s_hi[BB];
    __shared__ int   s_dis[BB];
    __shared__ float s_c[BB];
    __shared__ int   s_nb[BB * KK];
    __shared__ float s_wt[BB * KK];
    int tid = threadIdx.x;

    {
        int r = rel[tid];
        int hi = head[tid];
        int dis = (r >= 4) && (r <= 6);
        s_hi[tid] = hi;
        s_dis[tid] = dis;
        if (dis) {
            int local = g2l[hi];
            float deg = (float)g_cnt[(r - 4) * ND + local];
            s_c[tid] = 0.7f * __expf(-0.7f * deg) + 0.2f;
#pragma unroll
            for (int k = 0; k < KK; k++) {
                s_nb[tid * KK + k] = nb[local * KK + k];
                s_wt[tid * KK + k] = wts[local * KK + k];
            }
        }
    }
    __syncthreads();

    for (int t = 0; t < BB; t++) {
        if (!s_dis[t]) continue;
        int hi = s_hi[t];
        float c = s_c[t];
        float vec = 0.f;
#pragma unroll
        for (int k = 0; k < KK; k++)
            vec += s_wt[t * KK + k] * g_emb[(size_t)s_nb[t * KK + k] * 256 + tid];
        float cur = g_emb[(size_t)hi * 256 + tid];
        g_emb[(size_t)hi * 256 + tid] = c * vec + (1.f - c) * cur;
    }
}

// ---------------- DistMult decode + sigmoid ----------------
__global__ __launch_bounds__(256) void decode_kernel(const int* __restrict__ head,
                                                     const int* __restrict__ rel,
                                                     const int* __restrict__ tail,
                                                     const float* __restrict__ rel_emb,
                                                     float* __restrict__ out) {
    int w = (blockIdx.x * blockDim.x + threadIdx.x) >> 5;
    int lane = threadIdx.x & 31;
    if (w >= BB) return;
    int hi = head[w], ti = tail[w], r = rel[w];
    const float4* hp = (const float4*)(g_emb + (size_t)hi * 256);
    const float4* tp = (const float4*)(g_emb + (size_t)ti * 256);
    const float4* rp = (const float4*)(rel_emb + (size_t)r * 256);
    float4 h0 = hp[lane], h1 = hp[32 + lane];
    float4 t0 = tp[lane], t1 = tp[32 + lane];
    float4 r0 = rp[lane], r1 = rp[32 + lane];
    float s = h0.x * r0.x * t0.x + h0.y * r0.y * t0.y + h0.z * r0.z * t0.z + h0.w * r0.w * t0.w
            + h1.x * r1.x * t1.x + h1.y * r1.y * t1.y + h1.z * r1.z * t1.z + h1.w * r1.w * t1.w;
#pragma unroll
    for (int o = 16; o; o >>= 1) s += __shfl_xor_sync(0xffffffffu, s, o);
    if (lane == 0) out[w] = 1.f / (1.f + __expf(-s));
}

// ---------------- host launch ----------------
extern "C" void kernel_launch(void* const* d_in, const int* in_sizes, int n_in,
                              void* d_out, int out_size) {
    const float* x        = (const float*)d_in[0];
    const int*   eidx     = (const int*)d_in[1];
    const int*   head     = (const int*)d_in[2];
    const int*   rel      = (const int*)d_in[3];
    const int*   tail     = (const int*)d_in[4];
    const int*   g2l      = (const int*)d_in[5];
    const int*   reledge  = (const int*)d_in[6];
    const int*   simnb    = (const int*)d_in[7];
    const float* simw     = (const float*)d_in[8];
    const float* W1       = (const float*)d_in[9];
    const float* a1s      = (const float*)d_in[10];
    const float* a1d      = (const float*)d_in[11];
    const float* b1       = (const float*)d_in[12];
    const float* W2       = (const float*)d_in[13];
    const float* a2s      = (const float*)d_in[14];
    const float* a2d      = (const float*)d_in[15];
    const float* b2       = (const float*)d_in[16];
    const float* rel_emb  = (const float*)d_in[17];
    float* out = (float*)d_out;

    const int* src = eidx;
    const int* dst = eidx + EE;

    static cudaStream_t s2 = nullptr;
    static cudaEvent_t evFork = nullptr, evJoin = nullptr, evC0 = nullptr,
                       evG0 = nullptr, evScan = nullptr, evTail = nullptr;
    if (s2 == nullptr) {
        cudaStreamCreateWithFlags(&s2, cudaStreamNonBlocking);
        cudaEventCreateWithFlags(&evFork, cudaEventDisableTiming);
        cudaEventCreateWithFlags(&evJoin, cudaEventDisableTiming);
        cudaEventCreateWithFlags(&evC0, cudaEventDisableTiming);
        cudaEventCreateWithFlags(&evG0, cudaEventDisableTiming);
        cudaEventCreateWithFlags(&evScan, cudaEventDisableTiming);
        cudaEventCreateWithFlags(&evTail, cudaEventDisableTiming);
    }

    cudaFuncSetAttribute(gemm_tc<1>, cudaFuncAttributeMaxDynamicSharedMemorySize, SMEM_GEMM);
    cudaFuncSetAttribute(gemm_tc<2>, cudaFuncAttributeMaxDynamicSharedMemorySize, SMEM_GEMM);

    dim3 ggridFull(TILES_TOTAL, 2);
    dim3 ggridC0(TILES_C0, 2);
    dim3 ggridC1(TILES_C1, 2);
    auto aggBlocks = [](int nodes) { return (nodes * 32 + 255) / 256; };

    // ---- fork: CSR build chain on s2, prep+gemm1 on main ----
    cudaEventRecord(evFork, 0);
    cudaStreamWaitEvent(s2, evFork, 0);

    hist_kernel<<<(EE + 255) / 256, 256, 0, s2>>>(dst, reledge);
    partial_kernel<<<PB, 256, 0, s2>>>();
    rowptr_kernel<<<PB, 512, 0, s2>>>();
    scatter_kernel<<<(EE + 255) / 256, 256, 0, s2>>>(src, dst);
    cudaEventRecord(evJoin, s2);

    prep_all_kernel<<<(NN * HD + 255) / 256, 256>>>(x, W1, W2);
    gemm_tc<1><<<ggridFull, 256, SMEM_GEMM>>>(a1s, a1d, 0, NN);

    // ---- join: aggregate needs CSR + gemm1; chunked pipeline with gemm2 ----
    cudaStreamWaitEvent(0, evJoin, 0);
    gat_aggregate_kernel<1><<<aggBlocks(ROWS_C0), 256>>>(b1, 0, ROWS_C0);
    cudaEventRecord(evC0, 0);
    cudaStreamWaitEvent(s2, evC0, 0);
    gemm_tc<2><<<ggridC0, 256, SMEM_GEMM, s2>>>(a2s, a2d, 0, NN);       // overlaps agg1 c1
    cudaEventRecord(evG0, s2);

    gat_aggregate_kernel<1><<<aggBlocks(NN - ROWS_C0), 256>>>(b1, ROWS_C0, NN - ROWS_C0);
    gemm_tc<2><<<ggridC1, 256, SMEM_GEMM>>>(a2s, a2d, ROWS_C0, NN);
    cudaStreamWaitEvent(0, evG0, 0);

    gat_aggregate_kernel<2><<<aggBlocks(NN), 256>>>(b2, 0, NN);
    scan_seq_kernel<<<1, 256>>>(head, rel, g2l, simnb, simw);

    // ---- tail_zero overlaps decode ----
    cudaEventRecord(evScan, 0);
    cudaStreamWaitEvent(s2, evScan, 0);
    tail_zero_kernel<<<(NN + 255) / 256, 256, 0, s2>>>();
    cudaEventRecord(evTail, s2);

    decode_kernel<<<(BB * 32 + 255) / 256, 256>>>(head, rel, tail, rel_emb, out);
    cudaStreamWaitEvent(0, evTail, 0);
}

// round 14
// speedup vs baseline: 1.2889x; 1.2889x over previous
#include <cuda_runtime.h>
#include <cuda_fp16.h>
#include <mma.h>
#include <math.h>
#include <stdint.h>

using namespace nvcuda;

// ---------------- problem constants ----------------
constexpr int NN  = 50000;
constexpr int EE  = 800000;
constexpr int HD  = 256;
constexpr int BB  = 256;
constexpr int ND  = 5000;
constexpr int KK  = 16;
constexpr int ER  = 20000;

// ---------------- device scratch (zero-init at load; tail_zero restores each replay) ----
__device__ __align__(16) float g_h[(size_t)NN * HD];
__device__ __align__(16) float g_emb[(size_t)NN * HD];
__device__ __align__(16) __half g_xh[(size_t)NN * HD];
__device__ __align__(16) __half g_acth[(size_t)NN * HD];
__device__ __align__(16) __half g_w1h[256 * 256];
__device__ __align__(16) __half g_w2h[256 * 256];
__device__ float g_ssrcA[NN];
__device__ float g_sdstA[NN];
__device__ float g_ssrcB[NN];
__device__ float g_sdstB[NN];
__device__ int   g_deg[NN];
__device__ int   g_cursor[NN];
__device__ int   g_rowptr[NN + 1];
__device__ int   g_csr_src[EE];
__device__ int   g_cnt[3 * ND];

constexpr int PB = 128;
constexpr int CHUNK = (NN + PB - 1) / PB;  // 391
__device__ int g_part[PB];

// ---------------- helpers ----------------
__device__ __forceinline__ uint32_t smem_u32(const void* p) {
    uint32_t a;
    asm("{ .reg .u64 t; cvta.to.shared.u64 t, %1; cvt.u32.u64 %0, t; }" : "=r"(a) : "l"(p));
    return a;
}
__device__ __forceinline__ void cp16(uint32_t dst, const void* src) {
    asm volatile("cp.async.cg.shared.global [%0], [%1], 16;" :: "r"(dst), "l"(src));
}

// ---------------- prep: x + W1/W2 fp16 conversion ----------------
__global__ void prep_all_kernel(const float* __restrict__ x,
                                const float* __restrict__ W1,
                                const float* __restrict__ W2) {
    int i = blockIdx.x * blockDim.x + threadIdx.x;
    if (i < NN * HD) g_xh[i] = __float2half(x[i]);
    if (i < 256 * 256) {
        g_w1h[i] = __float2half(W1[i]);
        g_w2h[i] = __float2half(W2[i]);
    }
    if (i == 0) g_rowptr[NN] = EE;
}

// ---------------- fused histograms (deg/cnt are zero on entry) ----------------
__global__ void hist_kernel(const int* __restrict__ dst, const int* __restrict__ res) {
    int e = blockIdx.x * blockDim.x + threadIdx.x;
    if (e < EE) atomicAdd(&g_deg[dst[e]], 1);
    if (e < 3 * ER) atomicAdd(&g_cnt[(e / ER) * ND + res[e]], 1);
}

__global__ void partial_kernel() {
    __shared__ int sh[256];
    int b = blockIdx.x, t = threadIdx.x;
    int base = b * CHUNK;
    int s = 0;
    for (int i = t; i < CHUNK; i += 256) {
        int idx = base + i;
        if (idx < NN) s += g_deg[idx];
    }
    sh[t] = s;
    __syncthreads();
    for (int off = 128; off; off >>= 1) {
        if (t < off) sh[t] += sh[t + off];
        __syncthreads();
    }
    if (t == 0) g_part[b] = sh[0];
}

__global__ void rowptr_kernel() {
    __shared__ int red[128];
    __shared__ int s[512];
    int b = blockIdx.x, t = threadIdx.x;
    if (t < 128) red[t] = (t < b) ? g_part[t] : 0;
    __syncthreads();
    for (int off = 64; off; off >>= 1) {
        if (t < off) red[t] += red[t + off];
        __syncthreads();
    }
    int base = red[0];
    int idx = b * CHUNK + t;
    int v = (t < CHUNK && idx < NN) ? g_deg[idx] : 0;
    s[t] = v;
    __syncthreads();
    for (int off = 1; off < 512; off <<= 1) {
        int u = (t >= off) ? s[t - off] : 0;
        __syncthreads();
        s[t] += u;
        __syncthreads();
    }
    if (t < CHUNK && idx < NN) g_rowptr[idx] = base + s[t] - v;
}

__global__ void scatter_kernel(const int* __restrict__ src, const int* __restrict__ dst) {
    int e = blockIdx.x * blockDim.x + threadIdx.x;
    if (e < EE) {
        int d = dst[e];
        int pos = atomicAdd(&g_cursor[d], 1);
        g_csr_src[g_rowptr[d] + pos] = src[e];
    }
}

// ---------------- tail state-restore (runs on s2, overlapped with decode) ----------
__global__ void tail_zero_kernel() {
    int i = blockIdx.x * blockDim.x + threadIdx.x;
    if (i < NN) {
        g_ssrcA[i] = 0.f; g_sdstA[i] = 0.f;
        g_ssrcB[i] = 0.f; g_sdstB[i] = 0.f;
        g_deg[i] = 0; g_cursor[i] = 0;
    }
    if (i < 3 * ND) g_cnt[i] = 0;
}

// ---------------- WMMA fp16 GEMM (single term), cp.async 2-buffer, fused dots ----
constexpr int BM = 128, BN = 128, KC = 32;
constexpr int LDA = KC + 8;   // 40 halves
constexpr int LDB = BN + 8;   // 136 halves
constexpr int SZ_A = BM * LDA * 2;  // 10240
constexpr int SZ_B = KC * LDB * 2;  // 8704
constexpr int OFF_A = 0;
constexpr int OFF_B = SZ_A;
constexpr int BUF = SZ_A + SZ_B;           // 18944
constexpr int SMEM_GEMM = 128 * 132 * 4;   // 67584 (epilogue tile; > 2*BUF)

template <int LAYER>
__global__ __launch_bounds__(256, 2) void gemm_tc(const float* __restrict__ asrc,
                                                  const float* __restrict__ adst, int M) {
    const __half* __restrict__ A = (LAYER == 1) ? g_xh : g_acth;
    const __half* __restrict__ W = (LAYER == 1) ? g_w1h : g_w2h;
    float* __restrict__ ssrc = (LAYER == 1) ? g_ssrcA : g_ssrcB;
    float* __restrict__ sdst = (LAYER == 1) ? g_sdstA : g_sdstB;

    extern __shared__ char smem[];
    uint32_t sb = smem_u32(smem);

    int tid = threadIdx.x;
    int wid = tid >> 5;
    int lane = tid & 31;
    int wm = wid & 3;
    int wn = wid >> 2;
    int row0 = blockIdx.x * BM;
    int col0 = blockIdx.y * BN;

    wmma::fragment<wmma::accumulator, 16, 16, 16, float> acc[2][4];
#pragma unroll
    for (int mt = 0; mt < 2; mt++)
#pragma unroll
        for (int nt = 0; nt < 4; nt++) wmma::fill_fragment(acc[mt][nt], 0.0f);

    auto load_chunk = [&](int c) {
        int kc = c * KC;
        uint32_t bb = sb + (c & 1) * BUF;
        // A: 128 rows x 32 halves = 512 x 16B; thread does 2
#pragma unroll
        for (int p = 0; p < 2; p++) {
            int t = p * 256 + tid;
            int r = t >> 2, seg = t & 3;
            int gr = row0 + r; if (gr >= M) gr = M - 1;
            cp16(bb + OFF_A + r * (LDA * 2) + seg * 16,
                 A + (size_t)gr * 256 + kc + seg * 8);
        }
        // B: 32 k-rows x 128 halves = 512 x 16B; thread does 2
#pragma unroll
        for (int p = 0; p < 2; p++) {
            int t = p * 256 + tid;
            int k = t >> 4, seg = t & 15;
            cp16(bb + OFF_B + k * (LDB * 2) + seg * 16,
                 W + (size_t)(kc + k) * 256 + col0 + seg * 8);
        }
        asm volatile("cp.async.commit_group;" ::: "memory");
    };

    load_chunk(0);

    for (int c = 0; c < 8; c++) {
        if (c < 7) {
            load_chunk(c + 1);
            asm volatile("cp.async.wait_group 1;" ::: "memory");
        } else {
            asm volatile("cp.async.wait_group 0;" ::: "memory");
        }
        __syncthreads();

        const char* buf = smem + (c & 1) * BUF;
        const __half* bA = (const __half*)(buf + OFF_A);
        const __half* bB = (const __half*)(buf + OFF_B);

#pragma unroll
        for (int s = 0; s < KC / 16; s++) {
            wmma::fragment<wmma::matrix_a, 16, 16, 16, __half, wmma::row_major> a[2];
#pragma unroll
            for (int mt = 0; mt < 2; mt++)
                wmma::load_matrix_sync(a[mt], bA + (wm * 32 + mt * 16) * LDA + s * 16, LDA);
#pragma unroll
            for (int nt = 0; nt < 4; nt++) {
                wmma::fragment<wmma::matrix_b, 16, 16, 16, __half, wmma::row_major> b;
                wmma::load_matrix_sync(b, bB + (s * 16) * LDB + wn * 64 + nt * 16, LDB);
#pragma unroll
                for (int mt = 0; mt < 2; mt++)
                    wmma::mma_sync(acc[mt][nt], a[mt], b, acc[mt][nt]);
            }
        }
        __syncthreads();
    }

    // ---- epilogue: stage C tile in smem, write g_h, fused partial dots ----
    float* smem_f = (float*)smem;  // 128 x 132 fp32 = 67584 B
#pragma unroll
    for (int mt = 0; mt < 2; mt++)
#pragma unroll
        for (int nt = 0; nt < 4; nt++)
            wmma::store_matrix_sync(smem_f + (wm * 32 + mt * 16) * 132 + wn * 64 + nt * 16,
                                    acc[mt][nt], 132, wmma::mem_row_major);
    __syncthreads();

    float4 af = *(const float4*)(asrc + col0 + lane * 4);
    float4 df = *(const float4*)(adst + col0 + lane * 4);
#pragma unroll 4
    for (int rr = 0; rr < 16; rr++) {
        int r = wid * 16 + rr;
        int grow = row0 + r;
        if (grow < M) {
            float4 v = *(float4*)(smem_f + r * 132 + lane * 4);
            *(float4*)(g_h + (size_t)grow * 256 + col0 + lane * 4) = v;
            float s1 = v.x * af.x + v.y * af.y + v.z * af.z + v.w * af.w;
            float s2 = v.x * df.x + v.y * df.y + v.z * df.z + v.w * df.w;
#pragma unroll
            for (int o = 16; o; o >>= 1) {
                s1 += __shfl_xor_sync(0xffffffffu, s1, o);
                s2 += __shfl_xor_sync(0xffffffffu, s2, o);
            }
            if (lane == 0) {
                atomicAdd(&ssrc[grow], s1);   // exactly 2 contributions -> deterministic
                atomicAdd(&sdst[grow], s2);
            }
        }
    }
}

// ---------------- fused GAT softmax + aggregation, warp per dst ----------
__device__ __forceinline__ float leaky02(float s) { return s > 0.f ? s : 0.2f * s; }

template <int LAYER>
__global__ __launch_bounds__(256) void gat_aggregate_kernel(const float* __restrict__ bias) {
    const float* __restrict__ ssrc = (LAYER == 1) ? g_ssrcA : g_ssrcB;
    const float* __restrict__ sdst = (LAYER == 1) ? g_sdstA : g_sdstB;

    int w = (blockIdx.x * blockDim.x + threadIdx.x) >> 5;
    int lane = threadIdx.x & 31;
    if (w >= NN) return;

    int base = g_rowptr[w];
    int d = g_rowptr[w + 1] - base;
    float4 acc0 = make_float4(0.f, 0.f, 0.f, 0.f);
    float4 acc1 = make_float4(0.f, 0.f, 0.f, 0.f);

    if (d > 0) {
        float sdv = sdst[w];
        int myidx = 0;
        float e = -1e30f;
        if (lane < d) {
            myidx = g_csr_src[base + lane];
            e = leaky02(ssrc[myidx] + sdv);
        }
        float mx = e;
        for (int i = 32 + lane; i < d; i += 32)
            mx = fmaxf(mx, leaky02(ssrc[g_csr_src[base + i]] + sdv));
#pragma unroll
        for (int o = 16; o; o >>= 1) mx = fmaxf(mx, __shfl_xor_sync(0xffffffffu, mx, o));
        float p = (lane < d) ? __expf(e - mx) : 0.f;
        float z = p;
        for (int i = 32 + lane; i < d; i += 32)
            z += __expf(leaky02(ssrc[g_csr_src[base + i]] + sdv) - mx);
#pragma unroll
        for (int o = 16; o; o >>= 1) z += __shfl_xor_sync(0xffffffffu, z, o);
        float invz = 1.f / (z + 1e-16f);
        float pn = p * invz;

        int dcap = d < 32 ? d : 32;
#pragma unroll 4
        for (int i = 0; i < dcap; i++) {
            float a = __shfl_sync(0xffffffffu, pn, i);
            int src = __shfl_sync(0xffffffffu, myidx, i);
            const float4* hp = (const float4*)(g_h + (size_t)src * 256);
            float4 v0 = hp[lane];
            float4 v1 = hp[32 + lane];
            acc0.x += a * v0.x; acc0.y += a * v0.y; acc0.z += a * v0.z; acc0.w += a * v0.w;
            acc1.x += a * v1.x; acc1.y += a * v1.y; acc1.z += a * v1.z; acc1.w += a * v1.w;
        }
        for (int i = 32; i < d; i++) {
            int src = g_csr_src[base + i];
            float a = __expf(leaky02(ssrc[src] + sdv) - mx) * invz;
            const float4* hp = (const float4*)(g_h + (size_t)src * 256);
            float4 v0 = hp[lane];
            float4 v1 = hp[32 + lane];
            acc0.x += a * v0.x; acc0.y += a * v0.y; acc0.z += a * v0.z; acc0.w += a * v0.w;
            acc1.x += a * v1.x; acc1.y += a * v1.y; acc1.z += a * v1.z; acc1.w += a * v1.w;
        }
    }

    const float4* b4 = (const float4*)bias;
    float4 bb0 = b4[lane], bb1 = b4[32 + lane];
    acc0.x += bb0.x; acc0.y += bb0.y; acc0.z += bb0.z; acc0.w += bb0.w;
    acc1.x += bb1.x; acc1.y += bb1.y; acc1.z += bb1.z; acc1.w += bb1.w;

    if (LAYER == 1) {
        float v[8] = {acc0.x, acc0.y, acc0.z, acc0.w, acc1.x, acc1.y, acc1.z, acc1.w};
#pragma unroll
        for (int j = 0; j < 8; j++) v[j] = v[j] / (1.f + __expf(-v[j]));
        size_t o0 = (size_t)w * 256 + lane * 4;
#pragma unroll
        for (int j = 0; j < 4; j++) g_acth[o0 + j] = __float2half(v[j]);
        size_t o1 = o0 + 128;
#pragma unroll
        for (int j = 0; j < 4; j++) g_acth[o1 + j] = __float2half(v[4 + j]);
    } else {
        float4* o4 = (float4*)(g_emb + (size_t)w * 256);
        o4[lane] = acc0;
        o4[32 + lane] = acc1;
    }
}

// ---------------- sequential per-triplet scan, smem-prefetched indices ----------------
__global__ void scan_seq_kernel(const int* __restrict__ head, const int* __restrict__ rel,
                                const int* __restrict__ g2l, const int* __restrict__ nb,
                                const float* __restrict__ wts) {
    __shared__ int   s_hi[BB];
    __shared__ int   s_dis[BB];
    __shared__ float s_c[BB];
    __shared__ int   s_nb[BB * KK];
    __shared__ float s_wt[BB * KK];
    int tid = threadIdx.x;

    {
        int r = rel[tid];
        int hi = head[tid];
        int dis = (r >= 4) && (r <= 6);
        s_hi[tid] = hi;
        s_dis[tid] = dis;
        if (dis) {
            int local = g2l[hi];
            float deg = (float)g_cnt[(r - 4) * ND + local];
            s_c[tid] = 0.7f * __expf(-0.7f * deg) + 0.2f;
#pragma unroll
            for (int k = 0; k < KK; k++) {
                s_nb[tid * KK + k] = nb[local * KK + k];
                s_wt[tid * KK + k] = wts[local * KK + k];
            }
        }
    }
    __syncthreads();

    for (int t = 0; t < BB; t++) {
        if (!s_dis[t]) continue;
        int hi = s_hi[t];
        float c = s_c[t];
        float vec = 0.f;
#pragma unroll
        for (int k = 0; k < KK; k++)
            vec += s_wt[t * KK + k] * g_emb[(size_t)s_nb[t * KK + k] * 256 + tid];
        float cur = g_emb[(size_t)hi * 256 + tid];
        g_emb[(size_t)hi * 256 + tid] = c * vec + (1.f - c) * cur;
    }
}

// ---------------- DistMult decode + sigmoid ----------------
__global__ __launch_bounds__(256) void decode_kernel(const int* __restrict__ head,
                                                     const int* __restrict__ rel,
                                                     const int* __restrict__ tail,
                                                     const float* __restrict__ rel_emb,
                                                     float* __restrict__ out) {
    int w = (blockIdx.x * blockDim.x + threadIdx.x) >> 5;
    int lane = threadIdx.x & 31;
    if (w >= BB) return;
    int hi = head[w], ti = tail[w], r = rel[w];
    const float4* hp = (const float4*)(g_emb + (size_t)hi * 256);
    const float4* tp = (const float4*)(g_emb + (size_t)ti * 256);
    const float4* rp = (const float4*)(rel_emb + (size_t)r * 256);
    float4 h0 = hp[lane], h1 = hp[32 + lane];
    float4 t0 = tp[lane], t1 = tp[32 + lane];
    float4 r0 = rp[lane], r1 = rp[32 + lane];
    float s = h0.x * r0.x * t0.x + h0.y * r0.y * t0.y + h0.z * r0.z * t0.z + h0.w * r0.w * t0.w
            + h1.x * r1.x * t1.x + h1.y * r1.y * t1.y + h1.z * r1.z * t1.z + h1.w * r1.w * t1.w;
#pragma unroll
    for (int o = 16; o; o >>= 1) s += __shfl_xor_sync(0xffffffffu, s, o);
    if (lane == 0) out[w] = 1.f / (1.f + __expf(-s));
}

// ---------------- host launch ----------------
extern "C" void kernel_launch(void* const* d_in, const int* in_sizes, int n_in,
                              void* d_out, int out_size) {
    const float* x        = (const float*)d_in[0];
    const int*   eidx     = (const int*)d_in[1];
    const int*   head     = (const int*)d_in[2];
    const int*   rel      = (const int*)d_in[3];
    const int*   tail     = (const int*)d_in[4];
    const int*   g2l      = (const int*)d_in[5];
    const int*   reledge  = (const int*)d_in[6];
    const int*   simnb    = (const int*)d_in[7];
    const float* simw     = (const float*)d_in[8];
    const float* W1       = (const float*)d_in[9];
    const float* a1s      = (const float*)d_in[10];
    const float* a1d      = (const float*)d_in[11];
    const float* b1       = (const float*)d_in[12];
    const float* W2       = (const float*)d_in[13];
    const float* a2s      = (const float*)d_in[14];
    const float* a2d      = (const float*)d_in[15];
    const float* b2       = (const float*)d_in[16];
    const float* rel_emb  = (const float*)d_in[17];
    float* out = (float*)d_out;

    const int* src = eidx;
    const int* dst = eidx + EE;

    static cudaStream_t s2 = nullptr;
    static cudaEvent_t evFork = nullptr, evJoin = nullptr, evScan = nullptr, evTail = nullptr;
    if (s2 == nullptr) {
        cudaStreamCreateWithFlags(&s2, cudaStreamNonBlocking);
        cudaEventCreateWithFlags(&evFork, cudaEventDisableTiming);
        cudaEventCreateWithFlags(&evJoin, cudaEventDisableTiming);
        cudaEventCreateWithFlags(&evScan, cudaEventDisableTiming);
        cudaEventCreateWithFlags(&evTail, cudaEventDisableTiming);
    }

    cudaFuncSetAttribute(gemm_tc<1>, cudaFuncAttributeMaxDynamicSharedMemorySize, SMEM_GEMM);
    cudaFuncSetAttribute(gemm_tc<2>, cudaFuncAttributeMaxDynamicSharedMemorySize, SMEM_GEMM);

    dim3 ggrid((NN + BM - 1) / BM, 2);
    int nwBlocks = (NN * 32 + 255) / 256;

    // ---- fork: CSR build chain on s2, prep+gemm1 on main ----
    cudaEventRecord(evFork, 0);
    cudaStreamWaitEvent(s2, evFork, 0);

    hist_kernel<<<(EE + 255) / 256, 256, 0, s2>>>(dst, reledge);
    partial_kernel<<<PB, 256, 0, s2>>>();
    rowptr_kernel<<<PB, 512, 0, s2>>>();
    scatter_kernel<<<(EE + 255) / 256, 256, 0, s2>>>(src, dst);
    cudaEventRecord(evJoin, s2);

    prep_all_kernel<<<(NN * HD + 255) / 256, 256>>>(x, W1, W2);
    gemm_tc<1><<<ggrid, 256, SMEM_GEMM>>>(a1s, a1d, NN);

    // ---- join: aggregate needs CSR + gemm1 ----
    cudaStreamWaitEvent(0, evJoin, 0);
    gat_aggregate_kernel<1><<<nwBlocks, 256>>>(b1);
    gemm_tc<2><<<ggrid, 256, SMEM_GEMM>>>(a2s, a2d, NN);
    gat_aggregate_kernel<2><<<nwBlocks, 256>>>(b2);
    scan_seq_kernel<<<1, 256>>>(head, rel, g2l, simnb, simw);

    // ---- tail_zero overlaps decode ----
    cudaEventRecord(evScan, 0);
    cudaStreamWaitEvent(s2, evScan, 0);
    tail_zero_kernel<<<(NN + 255) / 256, 256, 0, s2>>>();
    cudaEventRecord(evTail, s2);

    decode_kernel<<<(BB * 32 + 255) / 256, 256>>>(head, rel, tail, rel_emb, out);
    cudaStreamWaitEvent(0, evTail, 0);
}

// round 16
// speedup vs baseline: 1.4202x; 1.1018x over previous
#include <cuda_runtime.h>
#include <cuda_fp16.h>
#include <mma.h>
#include <math.h>
#include <stdint.h>

using namespace nvcuda;

// ---------------- problem constants ----------------
constexpr int NN  = 50000;
constexpr int EE  = 800000;
constexpr int HD  = 256;
constexpr int BB  = 256;
constexpr int ND  = 5000;
constexpr int KK  = 16;
constexpr int ER  = 20000;

// ---------------- device scratch (zero-init at load; tail_zero restores each replay) ----
__device__ __align__(16) __half g_h[(size_t)NN * HD];     // fp16 layer output (gather source)
__device__ __align__(16) float g_emb[(size_t)NN * HD];
__device__ __align__(16) __half g_xh[(size_t)NN * HD];
__device__ __align__(16) __half g_acth[(size_t)NN * HD];
__device__ __align__(16) __half g_w1h[256 * 256];
__device__ __align__(16) __half g_w2h[256 * 256];
__device__ float g_ssrcA[NN];
__device__ float g_sdstA[NN];
__device__ float g_ssrcB[NN];
__device__ float g_sdstB[NN];
__device__ int   g_deg[NN];
__device__ int   g_cursor[NN];
__device__ int   g_rowptr[NN + 1];
__device__ int   g_csr_src[EE];
__device__ int   g_cnt[3 * ND];

constexpr int PB = 128;
constexpr int CHUNK = (NN + PB - 1) / PB;  // 391
__device__ int g_part[PB];

// ---------------- helpers ----------------
__device__ __forceinline__ uint32_t smem_u32(const void* p) {
    uint32_t a;
    asm("{ .reg .u64 t; cvta.to.shared.u64 t, %1; cvt.u32.u64 %0, t; }" : "=r"(a) : "l"(p));
    return a;
}
__device__ __forceinline__ void cp16(uint32_t dst, const void* src) {
    asm volatile("cp.async.cg.shared.global [%0], [%1], 16;" :: "r"(dst), "l"(src));
}
__device__ __forceinline__ uint32_t h2_u32(__half2 h) {
    return *reinterpret_cast<uint32_t*>(&h);
}

// ---------------- prep: x + W1/W2 fp16 conversion ----------------
__global__ void prep_all_kernel(const float* __restrict__ x,
                                const float* __restrict__ W1,
                                const float* __restrict__ W2) {
    int i = blockIdx.x * blockDim.x + threadIdx.x;
    if (i < NN * HD) g_xh[i] = __float2half(x[i]);
    if (i < 256 * 256) {
        g_w1h[i] = __float2half(W1[i]);
        g_w2h[i] = __float2half(W2[i]);
    }
    if (i == 0) g_rowptr[NN] = EE;
}

// ---------------- fused histograms (deg/cnt are zero on entry) ----------------
__global__ void hist_kernel(const int* __restrict__ dst, const int* __restrict__ res) {
    int e = blockIdx.x * blockDim.x + threadIdx.x;
    if (e < EE) atomicAdd(&g_deg[dst[e]], 1);
    if (e < 3 * ER) atomicAdd(&g_cnt[(e / ER) * ND + res[e]], 1);
}

__global__ void partial_kernel() {
    __shared__ int sh[256];
    int b = blockIdx.x, t = threadIdx.x;
    int base = b * CHUNK;
    int s = 0;
    for (int i = t; i < CHUNK; i += 256) {
        int idx = base + i;
        if (idx < NN) s += g_deg[idx];
    }
    sh[t] = s;
    __syncthreads();
    for (int off = 128; off; off >>= 1) {
        if (t < off) sh[t] += sh[t + off];
        __syncthreads();
    }
    if (t == 0) g_part[b] = sh[0];
}

__global__ void rowptr_kernel() {
    __shared__ int red[128];
    __shared__ int s[512];
    int b = blockIdx.x, t = threadIdx.x;
    if (t < 128) red[t] = (t < b) ? g_part[t] : 0;
    __syncthreads();
    for (int off = 64; off; off >>= 1) {
        if (t < off) red[t] += red[t + off];
        __syncthreads();
    }
    int base = red[0];
    int idx = b * CHUNK + t;
    int v = (t < CHUNK && idx < NN) ? g_deg[idx] : 0;
    s[t] = v;
    __syncthreads();
    for (int off = 1; off < 512; off <<= 1) {
        int u = (t >= off) ? s[t - off] : 0;
        __syncthreads();
        s[t] += u;
        __syncthreads();
    }
    if (t < CHUNK && idx < NN) g_rowptr[idx] = base + s[t] - v;
}

__global__ void scatter_kernel(const int* __restrict__ src, const int* __restrict__ dst) {
    int e = blockIdx.x * blockDim.x + threadIdx.x;
    if (e < EE) {
        int d = dst[e];
        int pos = atomicAdd(&g_cursor[d], 1);
        g_csr_src[g_rowptr[d] + pos] = src[e];
    }
}

// ---------------- tail state-restore (runs on s2, overlapped with decode) ----------
__global__ void tail_zero_kernel() {
    int i = blockIdx.x * blockDim.x + threadIdx.x;
    if (i < NN) {
        g_ssrcA[i] = 0.f; g_sdstA[i] = 0.f;
        g_ssrcB[i] = 0.f; g_sdstB[i] = 0.f;
        g_deg[i] = 0; g_cursor[i] = 0;
    }
    if (i < 3 * ND) g_cnt[i] = 0;
}

// ---------------- WMMA fp16 GEMM (single term), cp.async 2-buffer, fused dots ----
constexpr int BM = 128, BN = 128, KC = 32;
constexpr int LDA = KC + 8;   // 40 halves
constexpr int LDB = BN + 8;   // 136 halves
constexpr int SZ_A = BM * LDA * 2;  // 10240
constexpr int SZ_B = KC * LDB * 2;  // 8704
constexpr int OFF_A = 0;
constexpr int OFF_B = SZ_A;
constexpr int BUF = SZ_A + SZ_B;           // 18944
constexpr int SMEM_GEMM = 128 * 132 * 4;   // 67584 (epilogue tile; > 2*BUF)

template <int LAYER>
__global__ __launch_bounds__(256, 2) void gemm_tc(const float* __restrict__ asrc,
                                                  const float* __restrict__ adst, int M) {
    const __half* __restrict__ A = (LAYER == 1) ? g_xh : g_acth;
    const __half* __restrict__ W = (LAYER == 1) ? g_w1h : g_w2h;
    float* __restrict__ ssrc = (LAYER == 1) ? g_ssrcA : g_ssrcB;
    float* __restrict__ sdst = (LAYER == 1) ? g_sdstA : g_sdstB;

    extern __shared__ char smem[];
    uint32_t sb = smem_u32(smem);

    int tid = threadIdx.x;
    int wid = tid >> 5;
    int lane = tid & 31;
    int wm = wid & 3;
    int wn = wid >> 2;
    int row0 = blockIdx.x * BM;
    int col0 = blockIdx.y * BN;

    wmma::fragment<wmma::accumulator, 16, 16, 16, float> acc[2][4];
#pragma unroll
    for (int mt = 0; mt < 2; mt++)
#pragma unroll
        for (int nt = 0; nt < 4; nt++) wmma::fill_fragment(acc[mt][nt], 0.0f);

    auto load_chunk = [&](int c) {
        int kc = c * KC;
        uint32_t bb = sb + (c & 1) * BUF;
#pragma unroll
        for (int p = 0; p < 2; p++) {
            int t = p * 256 + tid;
            int r = t >> 2, seg = t & 3;
            int gr = row0 + r; if (gr >= M) gr = M - 1;
            cp16(bb + OFF_A + r * (LDA * 2) + seg * 16,
                 A + (size_t)gr * 256 + kc + seg * 8);
        }
#pragma unroll
        for (int p = 0; p < 2; p++) {
            int t = p * 256 + tid;
            int k = t >> 4, seg = t & 15;
            cp16(bb + OFF_B + k * (LDB * 2) + seg * 16,
                 W + (size_t)(kc + k) * 256 + col0 + seg * 8);
        }
        asm volatile("cp.async.commit_group;" ::: "memory");
    };

    load_chunk(0);

    for (int c = 0; c < 8; c++) {
        if (c < 7) {
            load_chunk(c + 1);
            asm volatile("cp.async.wait_group 1;" ::: "memory");
        } else {
            asm volatile("cp.async.wait_group 0;" ::: "memory");
        }
        __syncthreads();

        const char* buf = smem + (c & 1) * BUF;
        const __half* bA = (const __half*)(buf + OFF_A);
        const __half* bB = (const __half*)(buf + OFF_B);

#pragma unroll
        for (int s = 0; s < KC / 16; s++) {
            wmma::fragment<wmma::matrix_a, 16, 16, 16, __half, wmma::row_major> a[2];
#pragma unroll
            for (int mt = 0; mt < 2; mt++)
                wmma::load_matrix_sync(a[mt], bA + (wm * 32 + mt * 16) * LDA + s * 16, LDA);
#pragma unroll
            for (int nt = 0; nt < 4; nt++) {
                wmma::fragment<wmma::matrix_b, 16, 16, 16, __half, wmma::row_major> b;
                wmma::load_matrix_sync(b, bB + (s * 16) * LDB + wn * 64 + nt * 16, LDB);
#pragma unroll
                for (int mt = 0; mt < 2; mt++)
                    wmma::mma_sync(acc[mt][nt], a[mt], b, acc[mt][nt]);
            }
        }
        __syncthreads();
    }

    // ---- epilogue: stage C tile in smem, write g_h (fp16), fused partial dots ----
    float* smem_f = (float*)smem;  // 128 x 132 fp32 = 67584 B
#pragma unroll
    for (int mt = 0; mt < 2; mt++)
#pragma unroll
        for (int nt = 0; nt < 4; nt++)
            wmma::store_matrix_sync(smem_f + (wm * 32 + mt * 16) * 132 + wn * 64 + nt * 16,
                                    acc[mt][nt], 132, wmma::mem_row_major);
    __syncthreads();

    float4 af = *(const float4*)(asrc + col0 + lane * 4);
    float4 df = *(const float4*)(adst + col0 + lane * 4);
#pragma unroll 4
    for (int rr = 0; rr < 16; rr++) {
        int r = wid * 16 + rr;
        int grow = row0 + r;
        if (grow < M) {
            float4 v = *(float4*)(smem_f + r * 132 + lane * 4);
            // write fp16 (4 halves = 8B) computed from fp32 accum
            uint2 hv = make_uint2(h2_u32(__floats2half2_rn(v.x, v.y)),
                                  h2_u32(__floats2half2_rn(v.z, v.w)));
            *(uint2*)(g_h + (size_t)grow * 256 + col0 + lane * 4) = hv;
            float s1 = v.x * af.x + v.y * af.y + v.z * af.z + v.w * af.w;
            float s2 = v.x * df.x + v.y * df.y + v.z * df.z + v.w * df.w;
#pragma unroll
            for (int o = 16; o; o >>= 1) {
                s1 += __shfl_xor_sync(0xffffffffu, s1, o);
                s2 += __shfl_xor_sync(0xffffffffu, s2, o);
            }
            if (lane == 0) {
                atomicAdd(&ssrc[grow], s1);   // exactly 2 contributions -> deterministic
                atomicAdd(&sdst[grow], s2);
            }
        }
    }
}

// ---------------- fused GAT softmax + aggregation, warp per dst, fp16 gather ----------
__device__ __forceinline__ float leaky02(float s) { return s > 0.f ? s : 0.2f * s; }

template <int LAYER>
__global__ __launch_bounds__(256) void gat_aggregate_kernel(const float* __restrict__ bias) {
    const float* __restrict__ ssrc = (LAYER == 1) ? g_ssrcA : g_ssrcB;
    const float* __restrict__ sdst = (LAYER == 1) ? g_sdstA : g_sdstB;

    int w = (blockIdx.x * blockDim.x + threadIdx.x) >> 5;
    int lane = threadIdx.x & 31;
    if (w >= NN) return;

    // lane owns 8 contiguous columns [lane*8, lane*8+8)
    float acc[8];
#pragma unroll
    for (int j = 0; j < 8; j++) acc[j] = 0.f;

    int base = g_rowptr[w];
    int d = g_rowptr[w + 1] - base;

    if (d > 0) {
        float sdv = sdst[w];
        int myidx = 0;
        float e = -1e30f;
        if (lane < d) {
            myidx = g_csr_src[base + lane];
            e = leaky02(ssrc[myidx] + sdv);
        }
        float mx = e;
        for (int i = 32 + lane; i < d; i += 32)
            mx = fmaxf(mx, leaky02(ssrc[g_csr_src[base + i]] + sdv));
#pragma unroll
        for (int o = 16; o; o >>= 1) mx = fmaxf(mx, __shfl_xor_sync(0xffffffffu, mx, o));
        float p = (lane < d) ? __expf(e - mx) : 0.f;
        float z = p;
        for (int i = 32 + lane; i < d; i += 32)
            z += __expf(leaky02(ssrc[g_csr_src[base + i]] + sdv) - mx);
#pragma unroll
        for (int o = 16; o; o >>= 1) z += __shfl_xor_sync(0xffffffffu, z, o);
        float invz = 1.f / (z + 1e-16f);
        float pn = p * invz;

        int dcap = d < 32 ? d : 32;
#pragma unroll 4
        for (int i = 0; i < dcap; i++) {
            float a = __shfl_sync(0xffffffffu, pn, i);
            int src = __shfl_sync(0xffffffffu, myidx, i);
            uint4 hv = *(const uint4*)(g_h + (size_t)src * 256 + lane * 8);
            float2 f0 = __half22float2(*(__half2*)&hv.x);
            float2 f1 = __half22float2(*(__half2*)&hv.y);
            float2 f2 = __half22float2(*(__half2*)&hv.z);
            float2 f3 = __half22float2(*(__half2*)&hv.w);
            acc[0] += a * f0.x; acc[1] += a * f0.y;
            acc[2] += a * f1.x; acc[3] += a * f1.y;
            acc[4] += a * f2.x; acc[5] += a * f2.y;
            acc[6] += a * f3.x; acc[7] += a * f3.y;
        }
        for (int i = 32; i < d; i++) {
            int src = g_csr_src[base + i];
            float a = __expf(leaky02(ssrc[src] + sdv) - mx) * invz;
            uint4 hv = *(const uint4*)(g_h + (size_t)src * 256 + lane * 8);
            float2 f0 = __half22float2(*(__half2*)&hv.x);
            float2 f1 = __half22float2(*(__half2*)&hv.y);
            float2 f2 = __half22float2(*(__half2*)&hv.z);
            float2 f3 = __half22float2(*(__half2*)&hv.w);
            acc[0] += a * f0.x; acc[1] += a * f0.y;
            acc[2] += a * f1.x; acc[3] += a * f1.y;
            acc[4] += a * f2.x; acc[5] += a * f2.y;
            acc[6] += a * f3.x; acc[7] += a * f3.y;
        }
    }

    const float4* b4 = (const float4*)bias;
    float4 bb0 = b4[2 * lane], bb1 = b4[2 * lane + 1];
    acc[0] += bb0.x; acc[1] += bb0.y; acc[2] += bb0.z; acc[3] += bb0.w;
    acc[4] += bb1.x; acc[5] += bb1.y; acc[6] += bb1.z; acc[7] += bb1.w;

    if (LAYER == 1) {
#pragma unroll
        for (int j = 0; j < 8; j++) acc[j] = acc[j] / (1.f + __expf(-acc[j]));
        size_t o0 = (size_t)w * 256 + lane * 8;
#pragma unroll
        for (int j = 0; j < 8; j++) g_acth[o0 + j] = __float2half(acc[j]);
    } else {
        float4* o4 = (float4*)(g_emb + (size_t)w * 256);
        o4[2 * lane]     = make_float4(acc[0], acc[1], acc[2], acc[3]);
        o4[2 * lane + 1] = make_float4(acc[4], acc[5], acc[6], acc[7]);
    }
}

// ---------------- sequential per-triplet scan, smem-prefetched indices ----------------
__global__ void scan_seq_kernel(const int* __restrict__ head, const int* __restrict__ rel,
                                const int* __restrict__ g2l, const int* __restrict__ nb,
                                const float* __restrict__ wts) {
    __shared__ int   s_hi[BB];
    __shared__ int   s_dis[BB];
    __shared__ float s_c[BB];
    __shared__ int   s_nb[BB * KK];
    __shared__ float s_wt[BB * KK];
    int tid = threadIdx.x;

    {
        int r = rel[tid];
        int hi = head[tid];
        int dis = (r >= 4) && (r <= 6);
        s_hi[tid] = hi;
        s_dis[tid] = dis;
        if (dis) {
            int local = g2l[hi];
            float deg = (float)g_cnt[(r - 4) * ND + local];
            s_c[tid] = 0.7f * __expf(-0.7f * deg) + 0.2f;
#pragma unroll
            for (int k = 0; k < KK; k++) {
                s_nb[tid * KK + k] = nb[local * KK + k];
                s_wt[tid * KK + k] = wts[local * KK + k];
            }
        }
    }
    __syncthreads();

    for (int t = 0; t < BB; t++) {
        if (!s_dis[t]) continue;
        int hi = s_hi[t];
        float c = s_c[t];
        float vec = 0.f;
#pragma unroll
        for (int k = 0; k < KK; k++)
            vec += s_wt[t * KK + k] * g_emb[(size_t)s_nb[t * KK + k] * 256 + tid];
        float cur = g_emb[(size_t)hi * 256 + tid];
        g_emb[(size_t)hi * 256 + tid] = c * vec + (1.f - c) * cur;
    }
}

// ---------------- DistMult decode + sigmoid ----------------
__global__ __launch_bounds__(256) void decode_kernel(const int* __restrict__ head,
                                                     const int* __restrict__ rel,
                                                     const int* __restrict__ tail,
                                                     const float* __restrict__ rel_emb,
                                                     float* __restrict__ out) {
    int w = (blockIdx.x * blockDim.x + threadIdx.x) >> 5;
    int lane = threadIdx.x & 31;
    if (w >= BB) return;
    int hi = head[w], ti = tail[w], r = rel[w];
    const float4* hp = (const float4*)(g_emb + (size_t)hi * 256);
    const float4* tp = (const float4*)(g_emb + (size_t)ti * 256);
    const float4* rp = (const float4*)(rel_emb + (size_t)r * 256);
    float4 h0 = hp[lane], h1 = hp[32 + lane];
    float4 t0 = tp[lane], t1 = tp[32 + lane];
    float4 r0 = rp[lane], r1 = rp[32 + lane];
    float s = h0.x * r0.x * t0.x + h0.y * r0.y * t0.y + h0.z * r0.z * t0.z + h0.w * r0.w * t0.w
            + h1.x * r1.x * t1.x + h1.y * r1.y * t1.y + h1.z * r1.z * t1.z + h1.w * r1.w * t1.w;
#pragma unroll
    for (int o = 16; o; o >>= 1) s += __shfl_xor_sync(0xffffffffu, s, o);
    if (lane == 0) out[w] = 1.f / (1.f + __expf(-s));
}

// ---------------- host launch ----------------
extern "C" void kernel_launch(void* const* d_in, const int* in_sizes, int n_in,
                              void* d_out, int out_size) {
    const float* x        = (const float*)d_in[0];
    const int*   eidx     = (const int*)d_in[1];
    const int*   head     = (const int*)d_in[2];
    const int*   rel      = (const int*)d_in[3];
    const int*   tail     = (const int*)d_in[4];
    const int*   g2l      = (const int*)d_in[5];
    const int*   reledge  = (const int*)d_in[6];
    const int*   simnb    = (const int*)d_in[7];
    const float* simw     = (const float*)d_in[8];
    const float* W1       = (const float*)d_in[9];
    const float* a1s      = (const float*)d_in[10];
    const float* a1d      = (const float*)d_in[11];
    const float* b1       = (const float*)d_in[12];
    const float* W2       = (const float*)d_in[13];
    const float* a2s      = (const float*)d_in[14];
    const float* a2d      = (const float*)d_in[15];
    const float* b2       = (const float*)d_in[16];
    const float* rel_emb  = (const float*)d_in[17];
    float* out = (float*)d_out;

    const int* src = eidx;
    const int* dst = eidx + EE;

    static cudaStream_t s2 = nullptr;
    static cudaEvent_t evFork = nullptr, evJoin = nullptr, evScan = nullptr, evTail = nullptr;
    if (s2 == nullptr) {
        cudaStreamCreateWithFlags(&s2, cudaStreamNonBlocking);
        cudaEventCreateWithFlags(&evFork, cudaEventDisableTiming);
        cudaEventCreateWithFlags(&evJoin, cudaEventDisableTiming);
        cudaEventCreateWithFlags(&evScan, cudaEventDisableTiming);
        cudaEventCreateWithFlags(&evTail, cudaEventDisableTiming);
    }

    cudaFuncSetAttribute(gemm_tc<1>, cudaFuncAttributeMaxDynamicSharedMemorySize, SMEM_GEMM);
    cudaFuncSetAttribute(gemm_tc<2>, cudaFuncAttributeMaxDynamicSharedMemorySize, SMEM_GEMM);

    dim3 ggrid((NN + BM - 1) / BM, 2);
    int nwBlocks = (NN * 32 + 255) / 256;

    // ---- fork: CSR build chain on s2, prep+gemm1 on main ----
    cudaEventRecord(evFork, 0);
    cudaStreamWaitEvent(s2, evFork, 0);

    hist_kernel<<<(EE + 255) / 256, 256, 0, s2>>>(dst, reledge);
    partial_kernel<<<PB, 256, 0, s2>>>();
    rowptr_kernel<<<PB, 512, 0, s2>>>();
    scatter_kernel<<<(EE + 255) / 256, 256, 0, s2>>>(src, dst);
    cudaEventRecord(evJoin, s2);

    prep_all_kernel<<<(NN * HD + 255) / 256, 256>>>(x, W1, W2);
    gemm_tc<1><<<ggrid, 256, SMEM_GEMM>>>(a1s, a1d, NN);

    // ---- join: aggregate needs CSR + gemm1 ----
    cudaStreamWaitEvent(0, evJoin, 0);
    gat_aggregate_kernel<1><<<nwBlocks, 256>>>(b1);
    gemm_tc<2><<<ggrid, 256, SMEM_GEMM>>>(a2s, a2d, NN);
    gat_aggregate_kernel<2><<<nwBlocks, 256>>>(b2);
    scan_seq_kernel<<<1, 256>>>(head, rel, g2l, simnb, simw);

    // ---- tail_zero overlaps decode ----
    cudaEventRecord(evScan, 0);
    cudaStreamWaitEvent(s2, evScan, 0);
    tail_zero_kernel<<<(NN + 255) / 256, 256, 0, s2>>>();
    cudaEventRecord(evTail, s2);

    decode_kernel<<<(BB * 32 + 255) / 256, 256>>>(head, rel, tail, rel_emb, out);
    cudaStreamWaitEvent(0, evTail, 0);
}

// round 17
// speedup vs baseline: 1.4499x; 1.0209x over previous
#include <cuda_runtime.h>
#include <cuda_fp16.h>
#include <mma.h>
#include <math.h>
#include <stdint.h>

using namespace nvcuda;

// ---------------- problem constants ----------------
constexpr int NN  = 50000;
constexpr int EE  = 800000;
constexpr int HD  = 256;
constexpr int BB  = 256;
constexpr int ND  = 5000;
constexpr int KK  = 16;
constexpr int ER  = 20000;

// ---------------- device scratch (zero-init at load; tail_zero restores each replay) ----
__device__ __align__(16) __half g_h[(size_t)NN * HD];     // fp16 layer output (gather source)
__device__ __align__(16) float g_emb[(size_t)NN * HD];
__device__ __align__(16) __half g_xh[(size_t)NN * HD];
__device__ __align__(16) __half g_acth[(size_t)NN * HD];
__device__ __align__(16) __half g_w1h[256 * 256];
__device__ __align__(16) __half g_w2h[256 * 256];
__device__ float g_ssrcA[NN];
__device__ float g_sdstA[NN];
__device__ float g_ssrcB[NN];
__device__ float g_sdstB[NN];
__device__ int   g_deg[NN];
__device__ int   g_cursor[NN];
__device__ int   g_rowptr[NN + 1];
__device__ int   g_csr_src[EE];
__device__ int   g_cnt[3 * ND];

constexpr int PB = 128;
constexpr int CHUNK = (NN + PB - 1) / PB;  // 391
__device__ int g_part[PB];

// ---------------- helpers ----------------
__device__ __forceinline__ uint32_t smem_u32(const void* p) {
    uint32_t a;
    asm("{ .reg .u64 t; cvta.to.shared.u64 t, %1; cvt.u32.u64 %0, t; }" : "=r"(a) : "l"(p));
    return a;
}
__device__ __forceinline__ void cp16(uint32_t dst, const void* src) {
    asm volatile("cp.async.cg.shared.global [%0], [%1], 16;" :: "r"(dst), "l"(src));
}
__device__ __forceinline__ uint32_t h2_u32(__half2 h) {
    return *reinterpret_cast<uint32_t*>(&h);
}

// ---------------- prep: x + W1/W2 fp16 conversion ----------------
__global__ void prep_all_kernel(const float* __restrict__ x,
                                const float* __restrict__ W1,
                                const float* __restrict__ W2) {
    int i = blockIdx.x * blockDim.x + threadIdx.x;
    if (i < NN * HD) g_xh[i] = __float2half(x[i]);
    if (i < 256 * 256) {
        g_w1h[i] = __float2half(W1[i]);
        g_w2h[i] = __float2half(W2[i]);
    }
    if (i == 0) g_rowptr[NN] = EE;
}

// ---------------- fused histograms (deg/cnt are zero on entry) ----------------
__global__ void hist_kernel(const int* __restrict__ dst, const int* __restrict__ res) {
    int e = blockIdx.x * blockDim.x + threadIdx.x;
    if (e < EE) atomicAdd(&g_deg[dst[e]], 1);
    if (e < 3 * ER) atomicAdd(&g_cnt[(e / ER) * ND + res[e]], 1);
}

__global__ void partial_kernel() {
    __shared__ int sh[256];
    int b = blockIdx.x, t = threadIdx.x;
    int base = b * CHUNK;
    int s = 0;
    for (int i = t; i < CHUNK; i += 256) {
        int idx = base + i;
        if (idx < NN) s += g_deg[idx];
    }
    sh[t] = s;
    __syncthreads();
    for (int off = 128; off; off >>= 1) {
        if (t < off) sh[t] += sh[t + off];
        __syncthreads();
    }
    if (t == 0) g_part[b] = sh[0];
}

__global__ void rowptr_kernel() {
    __shared__ int red[128];
    __shared__ int s[512];
    int b = blockIdx.x, t = threadIdx.x;
    if (t < 128) red[t] = (t < b) ? g_part[t] : 0;
    __syncthreads();
    for (int off = 64; off; off >>= 1) {
        if (t < off) red[t] += red[t + off];
        __syncthreads();
    }
    int base = red[0];
    int idx = b * CHUNK + t;
    int v = (t < CHUNK && idx < NN) ? g_deg[idx] : 0;
    s[t] = v;
    __syncthreads();
    for (int off = 1; off < 512; off <<= 1) {
        int u = (t >= off) ? s[t - off] : 0;
        __syncthreads();
        s[t] += u;
        __syncthreads();
    }
    if (t < CHUNK && idx < NN) g_rowptr[idx] = base + s[t] - v;
}

__global__ void scatter_kernel(const int* __restrict__ src, const int* __restrict__ dst) {
    int e = blockIdx.x * blockDim.x + threadIdx.x;
    if (e < EE) {
        int d = dst[e];
        int pos = atomicAdd(&g_cursor[d], 1);
        g_csr_src[g_rowptr[d] + pos] = src[e];
    }
}

// ---------------- tail state-restore (runs on s2, overlapped with decode) ----------
__global__ void tail_zero_kernel() {
    int i = blockIdx.x * blockDim.x + threadIdx.x;
    if (i < NN) {
        g_ssrcA[i] = 0.f; g_sdstA[i] = 0.f;
        g_ssrcB[i] = 0.f; g_sdstB[i] = 0.f;
        g_deg[i] = 0; g_cursor[i] = 0;
    }
    if (i < 3 * ND) g_cnt[i] = 0;
}

// ---------------- WMMA fp16 GEMM (single term), KC=64, cp.async 2-buffer, fused dots ----
constexpr int BM = 128, BN = 128, KC = 64;
constexpr int LDA = KC + 8;   // 72 halves
constexpr int LDB = BN + 8;   // 136 halves
constexpr int SZ_A = BM * LDA * 2;  // 18432
constexpr int SZ_B = KC * LDB * 2;  // 17408
constexpr int OFF_A = 0;
constexpr int OFF_B = SZ_A;
constexpr int BUF = SZ_A + SZ_B;           // 35840
constexpr int SMEM_GEMM = 2 * BUF > 128 * 132 * 4 ? 2 * BUF : 128 * 132 * 4;  // 71680 vs 67584 -> 71680

template <int LAYER>
__global__ __launch_bounds__(256, 2) void gemm_tc(const float* __restrict__ asrc,
                                                  const float* __restrict__ adst, int M) {
    const __half* __restrict__ A = (LAYER == 1) ? g_xh : g_acth;
    const __half* __restrict__ W = (LAYER == 1) ? g_w1h : g_w2h;
    float* __restrict__ ssrc = (LAYER == 1) ? g_ssrcA : g_ssrcB;
    float* __restrict__ sdst = (LAYER == 1) ? g_sdstA : g_sdstB;

    extern __shared__ char smem[];
    uint32_t sb = smem_u32(smem);

    int tid = threadIdx.x;
    int wid = tid >> 5;
    int lane = tid & 31;
    int wm = wid & 3;
    int wn = wid >> 2;
    int row0 = blockIdx.x * BM;
    int col0 = blockIdx.y * BN;

    wmma::fragment<wmma::accumulator, 16, 16, 16, float> acc[2][4];
#pragma unroll
    for (int mt = 0; mt < 2; mt++)
#pragma unroll
        for (int nt = 0; nt < 4; nt++) wmma::fill_fragment(acc[mt][nt], 0.0f);

    auto load_chunk = [&](int c) {
        int kc = c * KC;
        uint32_t bb = sb + (c & 1) * BUF;
        // A: 128 rows x 64 halves = 1024 x 16B; thread does 4
#pragma unroll
        for (int p = 0; p < 4; p++) {
            int t = p * 256 + tid;
            int r = t >> 3, seg = t & 7;
            int gr = row0 + r; if (gr >= M) gr = M - 1;
            cp16(bb + OFF_A + r * (LDA * 2) + seg * 16,
                 A + (size_t)gr * 256 + kc + seg * 8);
        }
        // B: 64 k-rows x 128 halves = 1024 x 16B; thread does 4
#pragma unroll
        for (int p = 0; p < 4; p++) {
            int t = p * 256 + tid;
            int k = t >> 4, seg = t & 15;
            cp16(bb + OFF_B + k * (LDB * 2) + seg * 16,
                 W + (size_t)(kc + k) * 256 + col0 + seg * 8);
        }
        asm volatile("cp.async.commit_group;" ::: "memory");
    };

    load_chunk(0);

    for (int c = 0; c < 4; c++) {
        if (c < 3) {
            load_chunk(c + 1);
            asm volatile("cp.async.wait_group 1;" ::: "memory");
        } else {
            asm volatile("cp.async.wait_group 0;" ::: "memory");
        }
        __syncthreads();

        const char* buf = smem + (c & 1) * BUF;
        const __half* bA = (const __half*)(buf + OFF_A);
        const __half* bB = (const __half*)(buf + OFF_B);

#pragma unroll
        for (int s = 0; s < KC / 16; s++) {
            wmma::fragment<wmma::matrix_a, 16, 16, 16, __half, wmma::row_major> a[2];
#pragma unroll
            for (int mt = 0; mt < 2; mt++)
                wmma::load_matrix_sync(a[mt], bA + (wm * 32 + mt * 16) * LDA + s * 16, LDA);
#pragma unroll
            for (int nt = 0; nt < 4; nt++) {
                wmma::fragment<wmma::matrix_b, 16, 16, 16, __half, wmma::row_major> b;
                wmma::load_matrix_sync(b, bB + (s * 16) * LDB + wn * 64 + nt * 16, LDB);
#pragma unroll
                for (int mt = 0; mt < 2; mt++)
                    wmma::mma_sync(acc[mt][nt], a[mt], b, acc[mt][nt]);
            }
        }
        __syncthreads();
    }

    // ---- epilogue: stage C tile in smem, write g_h (fp16), fused partial dots ----
    float* smem_f = (float*)smem;  // 128 x 132 fp32 = 67584 B
#pragma unroll
    for (int mt = 0; mt < 2; mt++)
#pragma unroll
        for (int nt = 0; nt < 4; nt++)
            wmma::store_matrix_sync(smem_f + (wm * 32 + mt * 16) * 132 + wn * 64 + nt * 16,
                                    acc[mt][nt], 132, wmma::mem_row_major);
    __syncthreads();

    float4 af = *(const float4*)(asrc + col0 + lane * 4);
    float4 df = *(const float4*)(adst + col0 + lane * 4);
#pragma unroll 4
    for (int rr = 0; rr < 16; rr++) {
        int r = wid * 16 + rr;
        int grow = row0 + r;
        if (grow < M) {
            float4 v = *(float4*)(smem_f + r * 132 + lane * 4);
            uint2 hv = make_uint2(h2_u32(__floats2half2_rn(v.x, v.y)),
                                  h2_u32(__floats2half2_rn(v.z, v.w)));
            *(uint2*)(g_h + (size_t)grow * 256 + col0 + lane * 4) = hv;
            float s1 = v.x * af.x + v.y * af.y + v.z * af.z + v.w * af.w;
            float s2 = v.x * df.x + v.y * df.y + v.z * df.z + v.w * df.w;
#pragma unroll
            for (int o = 16; o; o >>= 1) {
                s1 += __shfl_xor_sync(0xffffffffu, s1, o);
                s2 += __shfl_xor_sync(0xffffffffu, s2, o);
            }
            if (lane == 0) {
                atomicAdd(&ssrc[grow], s1);   // exactly 2 contributions -> deterministic
                atomicAdd(&sdst[grow], s2);
            }
        }
    }
}

// ---------------- fused GAT softmax + aggregation, warp per dst, fp16 gather ----------
__device__ __forceinline__ float leaky02(float s) { return s > 0.f ? s : 0.2f * s; }

template <int LAYER>
__global__ __launch_bounds__(256) void gat_aggregate_kernel(const float* __restrict__ bias) {
    const float* __restrict__ ssrc = (LAYER == 1) ? g_ssrcA : g_ssrcB;
    const float* __restrict__ sdst = (LAYER == 1) ? g_sdstA : g_sdstB;

    int w = (blockIdx.x * blockDim.x + threadIdx.x) >> 5;
    int lane = threadIdx.x & 31;
    if (w >= NN) return;

    // lane owns 8 contiguous columns [lane*8, lane*8+8)
    float acc[8];
#pragma unroll
    for (int j = 0; j < 8; j++) acc[j] = 0.f;

    int base = g_rowptr[w];
    int d = g_rowptr[w + 1] - base;

    if (d > 0) {
        float sdv = sdst[w];
        int myidx = 0;
        float e = -1e30f;
        if (lane < d) {
            myidx = g_csr_src[base + lane];
            e = leaky02(ssrc[myidx] + sdv);
        }
        float mx = e;
        for (int i = 32 + lane; i < d; i += 32)
            mx = fmaxf(mx, leaky02(ssrc[g_csr_src[base + i]] + sdv));
#pragma unroll
        for (int o = 16; o; o >>= 1) mx = fmaxf(mx, __shfl_xor_sync(0xffffffffu, mx, o));
        float p = (lane < d) ? __expf(e - mx) : 0.f;
        float z = p;
        for (int i = 32 + lane; i < d; i += 32)
            z += __expf(leaky02(ssrc[g_csr_src[base + i]] + sdv) - mx);
#pragma unroll
        for (int o = 16; o; o >>= 1) z += __shfl_xor_sync(0xffffffffu, z, o);
        float invz = 1.f / (z + 1e-16f);
        float pn = p * invz;

        int dcap = d < 32 ? d : 32;
#pragma unroll 8
        for (int i = 0; i < dcap; i++) {
            float a = __shfl_sync(0xffffffffu, pn, i);
            int src = __shfl_sync(0xffffffffu, myidx, i);
            uint4 hv = *(const uint4*)(g_h + (size_t)src * 256 + lane * 8);
            float2 f0 = __half22float2(*(__half2*)&hv.x);
            float2 f1 = __half22float2(*(__half2*)&hv.y);
            float2 f2 = __half22float2(*(__half2*)&hv.z);
            float2 f3 = __half22float2(*(__half2*)&hv.w);
            acc[0] += a * f0.x; acc[1] += a * f0.y;
            acc[2] += a * f1.x; acc[3] += a * f1.y;
            acc[4] += a * f2.x; acc[5] += a * f2.y;
            acc[6] += a * f3.x; acc[7] += a * f3.y;
        }
#pragma unroll 4
        for (int i = 32; i < d; i++) {
            int src = g_csr_src[base + i];
            float a = __expf(leaky02(ssrc[src] + sdv) - mx) * invz;
            uint4 hv = *(const uint4*)(g_h + (size_t)src * 256 + lane * 8);
            float2 f0 = __half22float2(*(__half2*)&hv.x);
            float2 f1 = __half22float2(*(__half2*)&hv.y);
            float2 f2 = __half22float2(*(__half2*)&hv.z);
            float2 f3 = __half22float2(*(__half2*)&hv.w);
            acc[0] += a * f0.x; acc[1] += a * f0.y;
            acc[2] += a * f1.x; acc[3] += a * f1.y;
            acc[4] += a * f2.x; acc[5] += a * f2.y;
            acc[6] += a * f3.x; acc[7] += a * f3.y;
        }
    }

    const float4* b4 = (const float4*)bias;
    float4 bb0 = b4[2 * lane], bb1 = b4[2 * lane + 1];
    acc[0] += bb0.x; acc[1] += bb0.y; acc[2] += bb0.z; acc[3] += bb0.w;
    acc[4] += bb1.x; acc[5] += bb1.y; acc[6] += bb1.z; acc[7] += bb1.w;

    if (LAYER == 1) {
#pragma unroll
        for (int j = 0; j < 8; j++) acc[j] = acc[j] / (1.f + __expf(-acc[j]));
        size_t o0 = (size_t)w * 256 + lane * 8;
#pragma unroll
        for (int j = 0; j < 8; j++) g_acth[o0 + j] = __float2half(acc[j]);
    } else {
        float4* o4 = (float4*)(g_emb + (size_t)w * 256);
        o4[2 * lane]     = make_float4(acc[0], acc[1], acc[2], acc[3]);
        o4[2 * lane + 1] = make_float4(acc[4], acc[5], acc[6], acc[7]);
    }
}

// ---------------- sequential per-triplet scan, smem-prefetched indices ----------------
__global__ void scan_seq_kernel(const int* __restrict__ head, const int* __restrict__ rel,
                                const int* __restrict__ g2l, const int* __restrict__ nb,
                                const float* __restrict__ wts) {
    __shared__ int   s_hi[BB];
    __shared__ int   s_dis[BB];
    __shared__ float s_c[BB];
    __shared__ int   s_nb[BB * KK];
    __shared__ float s_wt[BB * KK];
    int tid = threadIdx.x;

    {
        int r = rel[tid];
        int hi = head[tid];
        int dis = (r >= 4) && (r <= 6);
        s_hi[tid] = hi;
        s_dis[tid] = dis;
        if (dis) {
            int local = g2l[hi];
            float deg = (float)g_cnt[(r - 4) * ND + local];
            s_c[tid] = 0.7f * __expf(-0.7f * deg) + 0.2f;
#pragma unroll
            for (int k = 0; k < KK; k++) {
                s_nb[tid * KK + k] = nb[local * KK + k];
                s_wt[tid * KK + k] = wts[local * KK + k];
            }
        }
    }
    __syncthreads();

    for (int t = 0; t < BB; t++) {
        if (!s_dis[t]) continue;
        int hi = s_hi[t];
        float c = s_c[t];
        float vec = 0.f;
#pragma unroll
        for (int k = 0; k < KK; k++)
            vec += s_wt[t * KK + k] * g_emb[(size_t)s_nb[t * KK + k] * 256 + tid];
        float cur = g_emb[(size_t)hi * 256 + tid];
        g_emb[(size_t)hi * 256 + tid] = c * vec + (1.f - c) * cur;
    }
}

// ---------------- DistMult decode + sigmoid ----------------
__global__ __launch_bounds__(256) void decode_kernel(const int* __restrict__ head,
                                                     const int* __restrict__ rel,
                                                     const int* __restrict__ tail,
                                                     const float* __restrict__ rel_emb,
                                                     float* __restrict__ out) {
    int w = (blockIdx.x * blockDim.x + threadIdx.x) >> 5;
    int lane = threadIdx.x & 31;
    if (w >= BB) return;
    int hi = head[w], ti = tail[w], r = rel[w];
    const float4* hp = (const float4*)(g_emb + (size_t)hi * 256);
    const float4* tp = (const float4*)(g_emb + (size_t)ti * 256);
    const float4* rp = (const float4*)(rel_emb + (size_t)r * 256);
    float4 h0 = hp[lane], h1 = hp[32 + lane];
    float4 t0 = tp[lane], t1 = tp[32 + lane];
    float4 r0 = rp[lane], r1 = rp[32 + lane];
    float s = h0.x * r0.x * t0.x + h0.y * r0.y * t0.y + h0.z * r0.z * t0.z + h0.w * r0.w * t0.w
            + h1.x * r1.x * t1.x + h1.y * r1.y * t1.y + h1.z * r1.z * t1.z + h1.w * r1.w * t1.w;
#pragma unroll
    for (int o = 16; o; o >>= 1) s += __shfl_xor_sync(0xffffffffu, s, o);
    if (lane == 0) out[w] = 1.f / (1.f + __expf(-s));
}

// ---------------- host launch ----------------
extern "C" void kernel_launch(void* const* d_in, const int* in_sizes, int n_in,
                              void* d_out, int out_size) {
    const float* x        = (const float*)d_in[0];
    const int*   eidx     = (const int*)d_in[1];
    const int*   head     = (const int*)d_in[2];
    const int*   rel      = (const int*)d_in[3];
    const int*   tail     = (const int*)d_in[4];
    const int*   g2l      = (const int*)d_in[5];
    const int*   reledge  = (const int*)d_in[6];
    const int*   simnb    = (const int*)d_in[7];
    const float* simw     = (const float*)d_in[8];
    const float* W1       = (const float*)d_in[9];
    const float* a1s      = (const float*)d_in[10];
    const float* a1d      = (const float*)d_in[11];
    const float* b1       = (const float*)d_in[12];
    const float* W2       = (const float*)d_in[13];
    const float* a2s      = (const float*)d_in[14];
    const float* a2d      = (const float*)d_in[15];
    const float* b2       = (const float*)d_in[16];
    const float* rel_emb  = (const float*)d_in[17];
    float* out = (float*)d_out;

    const int* src = eidx;
    const int* dst = eidx + EE;

    static cudaStream_t s2 = nullptr;
    static cudaEvent_t evFork = nullptr, evJoin = nullptr, evScan = nullptr, evTail = nullptr;
    if (s2 == nullptr) {
        cudaStreamCreateWithFlags(&s2, cudaStreamNonBlocking);
        cudaEventCreateWithFlags(&evFork, cudaEventDisableTiming);
        cudaEventCreateWithFlags(&evJoin, cudaEventDisableTiming);
        cudaEventCreateWithFlags(&evScan, cudaEventDisableTiming);
        cudaEventCreateWithFlags(&evTail, cudaEventDisableTiming);
    }

    cudaFuncSetAttribute(gemm_tc<1>, cudaFuncAttributeMaxDynamicSharedMemorySize, SMEM_GEMM);
    cudaFuncSetAttribute(gemm_tc<2>, cudaFuncAttributeMaxDynamicSharedMemorySize, SMEM_GEMM);

    dim3 ggrid((NN + BM - 1) / BM, 2);
    int nwBlocks = (NN * 32 + 255) / 256;

    // ---- fork: CSR build chain on s2, prep+gemm1 on main ----
    cudaEventRecord(evFork, 0);
    cudaStreamWaitEvent(s2, evFork, 0);

    hist_kernel<<<(EE + 255) / 256, 256, 0, s2>>>(dst, reledge);
    partial_kernel<<<PB, 256, 0, s2>>>();
    rowptr_kernel<<<PB, 512, 0, s2>>>();
    scatter_kernel<<<(EE + 255) / 256, 256, 0, s2>>>(src, dst);
    cudaEventRecord(evJoin, s2);

    prep_all_kernel<<<(NN * HD + 255) / 256, 256>>>(x, W1, W2);
    gemm_tc<1><<<ggrid, 256, SMEM_GEMM>>>(a1s, a1d, NN);

    // ---- join: aggregate needs CSR + gemm1 ----
    cudaStreamWaitEvent(0, evJoin, 0);
    gat_aggregate_kernel<1><<<nwBlocks, 256>>>(b1);
    gemm_tc<2><<<ggrid, 256, SMEM_GEMM>>>(a2s, a2d, NN);
    gat_aggregate_kernel<2><<<nwBlocks, 256>>>(b2);
    scan_seq_kernel<<<1, 256>>>(head, rel, g2l, simnb, simw);

    // ---- tail_zero overlaps decode ----
    cudaEventRecord(evScan, 0);
    cudaStreamWaitEvent(s2, evScan, 0);
    tail_zero_kernel<<<(NN + 255) / 256, 256, 0, s2>>>();
    cudaEventRecord(evTail, s2);

    decode_kernel<<<(BB * 32 + 255) / 256, 256>>>(head, rel, tail, rel_emb, out);
    cudaStreamWaitEvent(0, evTail, 0);
}